// round 1
// baseline (speedup 1.0000x reference)
#include <cuda_runtime.h>
#include <cuda_bf16.h>
#include <math.h>

// Problem constants
#define Bn   4
#define Tt   16
#define BT   64       // Bn*Tt
#define HIN  128
#define WIN  128
#define CIN  32
#define FF   64
#define C4F  256
#define H2   64
#define W2   64

// Scratch (no cudaMalloc allowed)
__device__ float g_xz[(size_t)BT * H2 * W2 * C4F];   // 256 MiB: input-conv results for all timesteps
__device__ float g_h[2][(size_t)Bn * H2 * W2 * FF];  // double-buffered hidden state
__device__ float g_c[(size_t)Bn * H2 * W2 * FF];     // cell state

// ---------------------------------------------------------------------------
// Zero-init h[0] and c
// ---------------------------------------------------------------------------
__global__ void init_state_kernel() {
    int i = blockIdx.x * blockDim.x + threadIdx.x;
    const int n = Bn * H2 * W2 * FF;
    if (i < n) {
        g_h[0][i] = 0.0f;
        g_c[i]    = 0.0f;
    }
}

// ---------------------------------------------------------------------------
// Input conv: x (BT,128,128,32) * W(3,3,32,256), stride 2, SAME (pad 0 before,
// 1 after) -> g_xz (BT,64,64,256).
// Block: 8x8 output tile, 64-out-channel slice. 256 threads:
//   tx = tid&63 (out channel), ts = tid>>6 (2 output rows each).
// ---------------------------------------------------------------------------
__global__ void __launch_bounds__(256) conv_in_kernel(
    const float* __restrict__ x, const float* __restrict__ Wt)
{
    const int bt  = blockIdx.z >> 2;
    const int cs  = blockIdx.z & 3;
    const int oy0 = blockIdx.y * 8;
    const int ox0 = blockIdx.x * 8;

    __shared__ float4 xs[17][17][8];   // 17x17 input window, 32 ci as 8 float4

    const int tid = threadIdx.x;

    // Cooperative load of the input tile (zero padding past the edge)
    for (int i = tid; i < 17 * 17 * 8; i += 256) {
        int ci4 = i & 7;
        int cc  = (i >> 3) % 17;
        int rr  = i / (17 * 8);
        int iy  = oy0 * 2 + rr;
        int ix  = ox0 * 2 + cc;
        float4 v = make_float4(0.f, 0.f, 0.f, 0.f);
        if (iy < HIN && ix < WIN) {
            v = *(const float4*)(x + ((((size_t)bt * HIN) + iy) * WIN + ix) * CIN + ci4 * 4);
        }
        xs[rr][cc][ci4] = v;
    }
    __syncthreads();

    const int tx = tid & 63;
    const int ts = tid >> 6;
    const int c  = cs * 64 + tx;

    float acc[2][8];
#pragma unroll
    for (int r = 0; r < 2; r++)
#pragma unroll
        for (int q = 0; q < 8; q++) acc[r][q] = 0.0f;

#pragma unroll 1
    for (int ky = 0; ky < 3; ky++) {
#pragma unroll 1
        for (int kx = 0; kx < 3; kx++) {
#pragma unroll 2
            for (int ci4 = 0; ci4 < 8; ci4++) {
                const float* wp = Wt + (((ky * 3 + kx) * CIN) + ci4 * 4) * C4F + c;
                float w0 = wp[0];
                float w1 = wp[C4F];
                float w2 = wp[2 * C4F];
                float w3 = wp[3 * C4F];
#pragma unroll
                for (int rr = 0; rr < 2; rr++) {
                    const int lr = ts * 2 + rr;
#pragma unroll
                    for (int cc = 0; cc < 8; cc++) {
                        float4 xv = xs[2 * lr + ky][2 * cc + kx][ci4];
                        acc[rr][cc] += w0 * xv.x;
                        acc[rr][cc] += w1 * xv.y;
                        acc[rr][cc] += w2 * xv.z;
                        acc[rr][cc] += w3 * xv.w;
                    }
                }
            }
        }
    }

#pragma unroll
    for (int rr = 0; rr < 2; rr++) {
        const int oy = oy0 + ts * 2 + rr;
#pragma unroll
        for (int cc = 0; cc < 8; cc++) {
            const int ox = ox0 + cc;
            g_xz[((((size_t)bt * H2) + oy) * W2 + ox) * C4F + c] = acc[rr][cc];
        }
    }
}

__device__ __forceinline__ float hsig(float z) {
    return fminf(fmaxf(0.2f * z + 0.5f, 0.0f), 1.0f);
}

// ---------------------------------------------------------------------------
// One LSTM timestep, fused: z = xz_t + conv(h_prev, U, s=1, SAME) + b,
// gate math, state update, BatchNorm-affine output.
// Block: 4x8 spatial tile for one batch, all 256 gate channels.
// Grid: (8 col-tiles, 16 row-tiles, 4 batch).
// ---------------------------------------------------------------------------
__global__ void __launch_bounds__(256) lstm_step_kernel(
    const float* __restrict__ U, const float* __restrict__ bvec,
    const float* __restrict__ gamma, const float* __restrict__ beta,
    const float* __restrict__ mmean, const float* __restrict__ mvar,
    float* __restrict__ out, int t)
{
    const int b  = blockIdx.z;
    const int y0 = blockIdx.y * 4;
    const int x0 = blockIdx.x * 8;

    __shared__ float4 hs[6][10][16];   // (4+2)x(8+2) tile, 64 ci as 16 float4 (15 KiB)
    __shared__ float  zs[32][C4F];     // z for 32 positions x 256 channels (32 KiB)

    const float* __restrict__ hprev = g_h[t & 1];
    float* __restrict__ hnext       = g_h[(t + 1) & 1];

    const int tid = threadIdx.x;

    // Load h tile with halo (zero-pad at image edges)
    for (int i = tid; i < 6 * 10 * 16; i += 256) {
        int ci4 = i & 15;
        int cc  = (i >> 4) % 10;
        int rr  = i / 160;
        int iy  = y0 + rr - 1;
        int ix  = x0 + cc - 1;
        float4 v = make_float4(0.f, 0.f, 0.f, 0.f);
        if (iy >= 0 && iy < H2 && ix >= 0 && ix < W2) {
            v = *(const float4*)(hprev + ((((size_t)b * H2) + iy) * W2 + ix) * FF + ci4 * 4);
        }
        hs[rr][cc][ci4] = v;
    }
    __syncthreads();

    const int co = tid;   // one of 256 gate channels

    float acc[4][8];
#pragma unroll
    for (int r = 0; r < 4; r++)
#pragma unroll
        for (int q = 0; q < 8; q++) acc[r][q] = 0.0f;

#pragma unroll 1
    for (int ky = 0; ky < 3; ky++) {
#pragma unroll 1
        for (int kx = 0; kx < 3; kx++) {
#pragma unroll 2
            for (int ci4 = 0; ci4 < 16; ci4++) {
                const float* up = U + (((ky * 3 + kx) * FF) + ci4 * 4) * C4F + co;
                float w0 = up[0];
                float w1 = up[C4F];
                float w2 = up[2 * C4F];
                float w3 = up[3 * C4F];
#pragma unroll
                for (int r = 0; r < 4; r++) {
#pragma unroll
                    for (int cc = 0; cc < 8; cc++) {
                        float4 hv = hs[r + ky][cc + kx][ci4];
                        acc[r][cc] += w0 * hv.x;
                        acc[r][cc] += w1 * hv.y;
                        acc[r][cc] += w2 * hv.z;
                        acc[r][cc] += w3 * hv.w;
                    }
                }
            }
        }
    }

    // z = conv(h) + xz_t + b  -> shared
    const float bv = bvec[co];
#pragma unroll
    for (int r = 0; r < 4; r++) {
        const int y = y0 + r;
#pragma unroll
        for (int cc = 0; cc < 8; cc++) {
            const int xw = x0 + cc;
            const size_t xzi =
                (((((size_t)b * Tt) + t) * H2 + y) * W2 + xw) * C4F + co;
            zs[r * 8 + cc][co] = acc[r][cc] + g_xz[xzi] + bv;
        }
    }
    __syncthreads();

    // Gate math: thread -> (f = tid&63, tile row pg = tid>>6), 8 columns each.
    const int f  = tid & 63;
    const int pg = tid >> 6;
    const float scale = gamma[f] * rsqrtf(mvar[f] + 1e-3f);
    const float shift = beta[f] - mmean[f] * scale;
    const int y = y0 + pg;

#pragma unroll
    for (int cc = 0; cc < 8; cc++) {
        const int p  = pg * 8 + cc;
        const int xw = x0 + cc;
        const float zi = zs[p][f];
        const float zf = zs[p][64 + f];
        const float zg = zs[p][128 + f];
        const float zo = zs[p][192 + f];

        const float ig = hsig(zi);
        const float fg = hsig(zf);
        const float og = hsig(zo);

        const size_t sidx = ((((size_t)b * H2) + y) * W2 + xw) * FF + f;
        const float cold = g_c[sidx];
        const float cn   = fg * cold + ig * tanhf(zg);
        const float hn   = og * tanhf(cn);

        g_c[sidx]   = cn;
        hnext[sidx] = hn;

        const size_t oidx =
            (((((size_t)b * Tt) + t) * H2 + y) * W2 + xw) * FF + f;
        out[oidx] = hn * scale + shift;
    }
}

// ---------------------------------------------------------------------------
extern "C" void kernel_launch(void* const* d_in, const int* in_sizes, int n_in,
                              void* d_out, int out_size)
{
    const float* x     = (const float*)d_in[0];
    const float* Wt    = (const float*)d_in[1];
    const float* U     = (const float*)d_in[2];
    const float* bvec  = (const float*)d_in[3];
    const float* gamma = (const float*)d_in[4];
    const float* beta  = (const float*)d_in[5];
    const float* mmean = (const float*)d_in[6];
    const float* mvar  = (const float*)d_in[7];
    float* out = (float*)d_out;

    (void)in_sizes; (void)n_in; (void)out_size;

    // Zero initial h and c
    {
        const int n = Bn * H2 * W2 * FF;
        init_state_kernel<<<(n + 255) / 256, 256>>>();
    }

    // Input-to-gate conv for all (b,t) at once
    {
        dim3 grid(8, 8, BT * 4);   // 8x8 spatial tiles, 4 channel slices per bt
        conv_in_kernel<<<grid, 256>>>(x, Wt);
    }

    // Sequential recurrence
    for (int t = 0; t < Tt; t++) {
        dim3 grid(8, 16, Bn);      // 8 col tiles, 16 row tiles, batch
        lstm_step_kernel<<<grid, 256>>>(U, bvec, gamma, beta, mmean, mvar, out, t);
    }
}

// round 2
// speedup vs baseline: 1.3361x; 1.3361x over previous
#include <cuda_runtime.h>
#include <cuda_bf16.h>
#include <math.h>

// Problem constants
#define Bn   4
#define Tt   16
#define BT   64       // Bn*Tt
#define HIN  128
#define WIN  128
#define CIN  32
#define FF   64
#define C4F  256
#define H2   64
#define W2   64

// Scratch (no cudaMalloc allowed)
__device__ float g_xz[(size_t)BT * H2 * W2 * C4F];   // input-conv results for all timesteps
__device__ float g_h[2][(size_t)Bn * H2 * W2 * FF];  // double-buffered hidden state
__device__ float g_c[(size_t)Bn * H2 * W2 * FF];     // cell state

// ---------------------------------------------------------------------------
// Zero-init h[0] and c
// ---------------------------------------------------------------------------
__global__ void init_state_kernel() {
    int i = blockIdx.x * blockDim.x + threadIdx.x;
    const int n = Bn * H2 * W2 * FF;
    if (i < n) {
        g_h[0][i] = 0.0f;
        g_c[i]    = 0.0f;
    }
}

// ---------------------------------------------------------------------------
// Input conv: x (BT,128,128,32) * W(3,3,32,256), stride 2, SAME -> g_xz.
// Block: 4x8 output tile for one bt. 256 threads:
//   c  = tid&63  -> handles out channels {c, c+64, c+128, c+192} (all 4 gates)
//   pg = tid>>6  -> output row y0+pg, 8 columns.
// Each LDS.128 of x feeds 16 FFMA.
// ---------------------------------------------------------------------------
__global__ void __launch_bounds__(256, 2) conv_in_kernel(
    const float* __restrict__ x, const float* __restrict__ Wt)
{
    const int bt  = blockIdx.z;
    const int y0  = blockIdx.y * 4;
    const int x0  = blockIdx.x * 8;

    __shared__ float4 xs[9][17][8];   // 9x17 input window, 32 ci as 8 float4

    const int tid = threadIdx.x;

    // Cooperative load of the input tile (zero padding past the edge)
    for (int i = tid; i < 9 * 17 * 8; i += 256) {
        int ci4 = i & 7;
        int cc  = (i >> 3) % 17;
        int rr  = i / (17 * 8);
        int iy  = y0 * 2 + rr;
        int ix  = x0 * 2 + cc;
        float4 v = make_float4(0.f, 0.f, 0.f, 0.f);
        if (iy < HIN && ix < WIN) {
            v = *(const float4*)(x + ((((size_t)bt * HIN) + iy) * WIN + ix) * CIN + ci4 * 4);
        }
        xs[rr][cc][ci4] = v;
    }
    __syncthreads();

    const int c  = tid & 63;
    const int pg = tid >> 6;

    float acc[4][8];
#pragma unroll
    for (int g = 0; g < 4; g++)
#pragma unroll
        for (int q = 0; q < 8; q++) acc[g][q] = 0.0f;

#pragma unroll 1
    for (int ky = 0; ky < 3; ky++) {
#pragma unroll 1
        for (int kx = 0; kx < 3; kx++) {
            const float* wp = Wt + (((ky * 3 + kx) * CIN)) * C4F + c;
#pragma unroll 2
            for (int ci4 = 0; ci4 < 8; ci4++) {
                float w[4][4];
#pragma unroll
                for (int j = 0; j < 4; j++)
#pragma unroll
                    for (int g = 0; g < 4; g++)
                        w[g][j] = wp[(ci4 * 4 + j) * C4F + g * 64];
#pragma unroll
                for (int cc = 0; cc < 8; cc++) {
                    float4 xv = xs[2 * pg + ky][2 * cc + kx][ci4];
#pragma unroll
                    for (int g = 0; g < 4; g++) {
                        acc[g][cc] += w[g][0] * xv.x;
                        acc[g][cc] += w[g][1] * xv.y;
                        acc[g][cc] += w[g][2] * xv.z;
                        acc[g][cc] += w[g][3] * xv.w;
                    }
                }
            }
        }
    }

    const int oy = y0 + pg;
#pragma unroll
    for (int cc = 0; cc < 8; cc++) {
        const int ox = x0 + cc;
        float* op = g_xz + ((((size_t)bt * H2) + oy) * W2 + ox) * C4F + c;
#pragma unroll
        for (int g = 0; g < 4; g++) op[g * 64] = acc[g][cc];
    }
}

__device__ __forceinline__ float hsig(float z) {
    return fminf(fmaxf(0.2f * z + 0.5f, 0.0f), 1.0f);
}

// ---------------------------------------------------------------------------
// One LSTM timestep, fused: z = xz_t + conv(h_prev, U, s=1, SAME) + b,
// gate math, state update, BatchNorm-affine output.
// Block: 4x8 spatial tile for one batch. 256 threads:
//   fch = tid&63 -> owns all 4 gates of feature channel fch
//   pg  = tid>>6 -> row y0+pg, 8 columns.
// All gates of a position live in-thread -> no z shared buffer needed.
// ---------------------------------------------------------------------------
__global__ void __launch_bounds__(256, 2) lstm_step_kernel(
    const float* __restrict__ U, const float* __restrict__ bvec,
    const float* __restrict__ gamma, const float* __restrict__ beta,
    const float* __restrict__ mmean, const float* __restrict__ mvar,
    float* __restrict__ out, int t)
{
    const int b  = blockIdx.z;
    const int y0 = blockIdx.y * 4;
    const int x0 = blockIdx.x * 8;

    __shared__ float4 hs[6][10][16];   // (4+2)x(8+2) tile, 64 ci as 16 float4

    const float* __restrict__ hprev = g_h[t & 1];
    float* __restrict__ hnext       = g_h[(t + 1) & 1];

    const int tid = threadIdx.x;

    // Load h tile with halo (zero-pad at image edges)
    for (int i = tid; i < 6 * 10 * 16; i += 256) {
        int ci4 = i & 15;
        int cc  = (i >> 4) % 10;
        int rr  = i / 160;
        int iy  = y0 + rr - 1;
        int ix  = x0 + cc - 1;
        float4 v = make_float4(0.f, 0.f, 0.f, 0.f);
        if (iy >= 0 && iy < H2 && ix >= 0 && ix < W2) {
            v = *(const float4*)(hprev + ((((size_t)b * H2) + iy) * W2 + ix) * FF + ci4 * 4);
        }
        hs[rr][cc][ci4] = v;
    }
    __syncthreads();

    const int fch = tid & 63;
    const int pg  = tid >> 6;

    float acc[4][8];
#pragma unroll
    for (int g = 0; g < 4; g++)
#pragma unroll
        for (int q = 0; q < 8; q++) acc[g][q] = 0.0f;

#pragma unroll 1
    for (int ky = 0; ky < 3; ky++) {
#pragma unroll 1
        for (int kx = 0; kx < 3; kx++) {
            const float* up = U + (((ky * 3 + kx) * FF)) * C4F + fch;
#pragma unroll 2
            for (int ci4 = 0; ci4 < 16; ci4++) {
                float w[4][4];
#pragma unroll
                for (int j = 0; j < 4; j++)
#pragma unroll
                    for (int g = 0; g < 4; g++)
                        w[g][j] = up[(ci4 * 4 + j) * C4F + g * 64];
#pragma unroll
                for (int cc = 0; cc < 8; cc++) {
                    float4 hv = hs[pg + ky][cc + kx][ci4];
#pragma unroll
                    for (int g = 0; g < 4; g++) {
                        acc[g][cc] += w[g][0] * hv.x;
                        acc[g][cc] += w[g][1] * hv.y;
                        acc[g][cc] += w[g][2] * hv.z;
                        acc[g][cc] += w[g][3] * hv.w;
                    }
                }
            }
        }
    }

    // Epilogue: gates -> state update -> BN-affine output. All in-thread.
    const float bi = bvec[fch];
    const float bf = bvec[64 + fch];
    const float bg = bvec[128 + fch];
    const float bo = bvec[192 + fch];
    const float scale = gamma[fch] * rsqrtf(mvar[fch] + 1e-3f);
    const float shift = beta[fch] - mmean[fch] * scale;
    const int y = y0 + pg;

#pragma unroll
    for (int cc = 0; cc < 8; cc++) {
        const int xw = x0 + cc;
        const float* xzp =
            g_xz + (((((size_t)b * Tt) + t) * H2 + y) * W2 + xw) * C4F + fch;

        const float zi = acc[0][cc] + xzp[0]   + bi;
        const float zf = acc[1][cc] + xzp[64]  + bf;
        const float zg = acc[2][cc] + xzp[128] + bg;
        const float zo = acc[3][cc] + xzp[192] + bo;

        const float ig = hsig(zi);
        const float fg = hsig(zf);
        const float og = hsig(zo);

        const size_t sidx = ((((size_t)b * H2) + y) * W2 + xw) * FF + fch;
        const float cold = g_c[sidx];
        const float cn   = fg * cold + ig * tanhf(zg);
        const float hn   = og * tanhf(cn);

        g_c[sidx]   = cn;
        hnext[sidx] = hn;

        const size_t oidx =
            (((((size_t)b * Tt) + t) * H2 + y) * W2 + xw) * FF + fch;
        out[oidx] = hn * scale + shift;
    }
}

// ---------------------------------------------------------------------------
extern "C" void kernel_launch(void* const* d_in, const int* in_sizes, int n_in,
                              void* d_out, int out_size)
{
    const float* x     = (const float*)d_in[0];
    const float* Wt    = (const float*)d_in[1];
    const float* U     = (const float*)d_in[2];
    const float* bvec  = (const float*)d_in[3];
    const float* gamma = (const float*)d_in[4];
    const float* beta  = (const float*)d_in[5];
    const float* mmean = (const float*)d_in[6];
    const float* mvar  = (const float*)d_in[7];
    float* out = (float*)d_out;

    (void)in_sizes; (void)n_in; (void)out_size;

    // Zero initial h and c
    {
        const int n = Bn * H2 * W2 * FF;
        init_state_kernel<<<(n + 255) / 256, 256>>>();
    }

    // Input-to-gate conv for all (b,t) at once
    {
        dim3 grid(8, 16, BT);      // 8 col tiles, 16 row tiles of 4, per bt
        conv_in_kernel<<<grid, 256>>>(x, Wt);
    }

    // Sequential recurrence
    for (int t = 0; t < Tt; t++) {
        dim3 grid(8, 16, Bn);      // 8 col tiles, 16 row tiles, batch
        lstm_step_kernel<<<grid, 256>>>(U, bvec, gamma, beta, mmean, mvar, out, t);
    }
}

// round 4
// speedup vs baseline: 1.4122x; 1.0569x over previous
#include <cuda_runtime.h>
#include <cuda_bf16.h>
#include <math.h>

// Problem constants
#define Bn   4
#define Tt   16
#define BT   64       // Bn*Tt
#define HIN  128
#define WIN  128
#define CIN  32
#define FF   64
#define C4F  256
#define H2   64
#define W2   64

// Scratch (no cudaMalloc allowed)
__device__ float g_xz[(size_t)BT * H2 * W2 * C4F];   // input-conv results for all timesteps
__device__ float g_h[2][(size_t)Bn * H2 * W2 * FF];  // double-buffered hidden state
__device__ float g_c[(size_t)Bn * H2 * W2 * FF];     // cell state

// ---- packed f32x2 helpers (FFMA2) -----------------------------------------
__device__ __forceinline__ void ffma2(unsigned long long& acc,
                                      unsigned long long a,
                                      unsigned long long b) {
    asm("fma.rn.f32x2 %0, %1, %2, %0;" : "+l"(acc) : "l"(a), "l"(b));
}
__device__ __forceinline__ unsigned long long pack2(float lo, float hi) {
    unsigned long long r;
    asm("mov.b64 %0, {%1, %2};" : "=l"(r) : "f"(lo), "f"(hi));
    return r;
}
__device__ __forceinline__ float hsum2(unsigned long long p) {
    float lo, hi;
    asm("mov.b64 {%0, %1}, %2;" : "=f"(lo), "=f"(hi) : "l"(p));
    return lo + hi;
}

// ---------------------------------------------------------------------------
// Zero-init h[0] and c
// ---------------------------------------------------------------------------
__global__ void init_state_kernel() {
    int i = blockIdx.x * blockDim.x + threadIdx.x;
    const int n = Bn * H2 * W2 * FF;
    if (i < n) {
        g_h[0][i] = 0.0f;
        g_c[i]    = 0.0f;
    }
}

// ---------------------------------------------------------------------------
// Input conv: x (BT,128,128,32) * W(3,3,32,256), stride 2, SAME -> g_xz.
// Block: 4x8 output tile for one bt. 256 threads:
//   c  = tid&63  -> out channels {c, c+64, c+128, c+192} (all 4 gates)
//   pg = tid>>6  -> output row y0+pg, 8 columns.
// Inner loops use packed f32x2 FMA over the ci reduction dim.
// ---------------------------------------------------------------------------
__global__ void __launch_bounds__(256, 2) conv_in_kernel(
    const float* __restrict__ x, const float* __restrict__ Wt)
{
    const int bt  = blockIdx.z;
    const int y0  = blockIdx.y * 4;
    const int x0  = blockIdx.x * 8;

    // 9x17 input window, 32 ci as 8 groups of 4 -> each entry = 2 f32x2 pairs
    __shared__ ulonglong2 xs[9][17][8];

    const int tid = threadIdx.x;

    for (int i = tid; i < 9 * 17 * 8; i += 256) {
        int ci4 = i & 7;
        int cc  = (i >> 3) % 17;
        int rr  = i / (17 * 8);
        int iy  = y0 * 2 + rr;
        int ix  = x0 * 2 + cc;
        float4 v = make_float4(0.f, 0.f, 0.f, 0.f);
        if (iy < HIN && ix < WIN) {
            v = *(const float4*)(x + ((((size_t)bt * HIN) + iy) * WIN + ix) * CIN + ci4 * 4);
        }
        *(float4*)&xs[rr][cc][ci4] = v;
    }
    __syncthreads();

    const int c  = tid & 63;
    const int pg = tid >> 6;

    unsigned long long acc[4][8];
#pragma unroll
    for (int g = 0; g < 4; g++)
#pragma unroll
        for (int q = 0; q < 8; q++) acc[g][q] = 0ULL;

#pragma unroll 1
    for (int ky = 0; ky < 3; ky++) {
#pragma unroll 1
        for (int kx = 0; kx < 3; kx++) {
            const float* wp = Wt + ((ky * 3 + kx) * CIN) * C4F + c;
#pragma unroll 2
            for (int ci4 = 0; ci4 < 8; ci4++) {
                unsigned long long wlo[4], whi[4];
#pragma unroll
                for (int g = 0; g < 4; g++) {
                    const float* wg = wp + (ci4 * 4) * C4F + g * 64;
                    wlo[g] = pack2(wg[0],        wg[C4F]);
                    whi[g] = pack2(wg[2 * C4F],  wg[3 * C4F]);
                }
#pragma unroll
                for (int cc = 0; cc < 8; cc++) {
                    ulonglong2 xv = xs[2 * pg + ky][2 * cc + kx][ci4];
#pragma unroll
                    for (int g = 0; g < 4; g++) {
                        ffma2(acc[g][cc], wlo[g], xv.x);
                        ffma2(acc[g][cc], whi[g], xv.y);
                    }
                }
            }
        }
    }

    const int oy = y0 + pg;
#pragma unroll
    for (int cc = 0; cc < 8; cc++) {
        const int ox = x0 + cc;
        float* op = g_xz + ((((size_t)bt * H2) + oy) * W2 + ox) * C4F + c;
#pragma unroll
        for (int g = 0; g < 4; g++) op[g * 64] = hsum2(acc[g][cc]);
    }
}

__device__ __forceinline__ float hsig(float z) {
    return fminf(fmaxf(0.2f * z + 0.5f, 0.0f), 1.0f);
}

// ---------------------------------------------------------------------------
// One LSTM timestep, fused: z = xz_t + conv(h_prev, U, s=1, SAME) + b,
// gate math, state update, BatchNorm-affine output.
// Block: 4x8 spatial tile, one batch. 256 threads:
//   fch = tid&63 -> owns all 4 gates of feature channel fch
//   pg  = tid>>6 -> row y0+pg, 8 columns.
// Packed f32x2 FMA over the ci reduction dim.
// ---------------------------------------------------------------------------
__global__ void __launch_bounds__(256, 2) lstm_step_kernel(
    const float* __restrict__ U, const float* __restrict__ bvec,
    const float* __restrict__ gamma, const float* __restrict__ beta,
    const float* __restrict__ mmean, const float* __restrict__ mvar,
    float* __restrict__ out, int t)
{
    const int b  = blockIdx.z;
    const int y0 = blockIdx.y * 4;
    const int x0 = blockIdx.x * 8;

    // (4+2)x(8+2) h tile, 64 ci as 16 groups of 4 -> 2 f32x2 pairs each
    __shared__ ulonglong2 hs[6][10][16];

    const float* __restrict__ hprev = g_h[t & 1];
    float* __restrict__ hnext       = g_h[(t + 1) & 1];

    const int tid = threadIdx.x;

    for (int i = tid; i < 6 * 10 * 16; i += 256) {
        int ci4 = i & 15;
        int cc  = (i >> 4) % 10;
        int rr  = i / 160;
        int iy  = y0 + rr - 1;
        int ix  = x0 + cc - 1;
        float4 v = make_float4(0.f, 0.f, 0.f, 0.f);
        if (iy >= 0 && iy < H2 && ix >= 0 && ix < W2) {
            v = *(const float4*)(hprev + ((((size_t)b * H2) + iy) * W2 + ix) * FF + ci4 * 4);
        }
        *(float4*)&hs[rr][cc][ci4] = v;
    }
    __syncthreads();

    const int fch = tid & 63;
    const int pg  = tid >> 6;

    unsigned long long acc[4][8];
#pragma unroll
    for (int g = 0; g < 4; g++)
#pragma unroll
        for (int q = 0; q < 8; q++) acc[g][q] = 0ULL;

#pragma unroll 1
    for (int ky = 0; ky < 3; ky++) {
#pragma unroll 1
        for (int kx = 0; kx < 3; kx++) {
            const float* up = U + ((ky * 3 + kx) * FF) * C4F + fch;
#pragma unroll 2
            for (int ci4 = 0; ci4 < 16; ci4++) {
                unsigned long long wlo[4], whi[4];
#pragma unroll
                for (int g = 0; g < 4; g++) {
                    const float* wg = up + (ci4 * 4) * C4F + g * 64;
                    wlo[g] = pack2(wg[0],       wg[C4F]);
                    whi[g] = pack2(wg[2 * C4F], wg[3 * C4F]);
                }
#pragma unroll
                for (int cc = 0; cc < 8; cc++) {
                    ulonglong2 hv = hs[pg + ky][cc + kx][ci4];
#pragma unroll
                    for (int g = 0; g < 4; g++) {
                        ffma2(acc[g][cc], wlo[g], hv.x);
                        ffma2(acc[g][cc], whi[g], hv.y);
                    }
                }
            }
        }
    }

    // Epilogue: gates -> state update -> BN-affine output. All in-thread.
    const float bi = bvec[fch];
    const float bf = bvec[64 + fch];
    const float bg = bvec[128 + fch];
    const float bo = bvec[192 + fch];
    const float scale = gamma[fch] * rsqrtf(mvar[fch] + 1e-3f);
    const float shift = beta[fch] - mmean[fch] * scale;
    const int y = y0 + pg;

#pragma unroll
    for (int cc = 0; cc < 8; cc++) {
        const int xw = x0 + cc;
        const float* xzp =
            g_xz + (((((size_t)b * Tt) + t) * H2 + y) * W2 + xw) * C4F + fch;

        const float zi = hsum2(acc[0][cc]) + xzp[0]   + bi;
        const float zf = hsum2(acc[1][cc]) + xzp[64]  + bf;
        const float zg = hsum2(acc[2][cc]) + xzp[128] + bg;
        const float zo = hsum2(acc[3][cc]) + xzp[192] + bo;

        const float ig = hsig(zi);
        const float fg = hsig(zf);
        const float og = hsig(zo);

        const size_t sidx = ((((size_t)b * H2) + y) * W2 + xw) * FF + fch;
        const float cold = g_c[sidx];
        const float cn   = fg * cold + ig * tanhf(zg);
        const float hn   = og * tanhf(cn);

        g_c[sidx]   = cn;
        hnext[sidx] = hn;

        const size_t oidx =
            (((((size_t)b * Tt) + t) * H2 + y) * W2 + xw) * FF + fch;
        out[oidx] = hn * scale + shift;
    }
}

// ---------------------------------------------------------------------------
extern "C" void kernel_launch(void* const* d_in, const int* in_sizes, int n_in,
                              void* d_out, int out_size)
{
    const float* x     = (const float*)d_in[0];
    const float* Wt    = (const float*)d_in[1];
    const float* U     = (const float*)d_in[2];
    const float* bvec  = (const float*)d_in[3];
    const float* gamma = (const float*)d_in[4];
    const float* beta  = (const float*)d_in[5];
    const float* mmean = (const float*)d_in[6];
    const float* mvar  = (const float*)d_in[7];
    float* out = (float*)d_out;

    (void)in_sizes; (void)n_in; (void)out_size;

    // Zero initial h and c
    {
        const int n = Bn * H2 * W2 * FF;
        init_state_kernel<<<(n + 255) / 256, 256>>>();
    }

    // Input-to-gate conv for all (b,t) at once
    {
        dim3 grid(8, 16, BT);      // 8 col tiles, 16 row tiles of 4, per bt
        conv_in_kernel<<<grid, 256>>>(x, Wt);
    }

    // Sequential recurrence
    for (int t = 0; t < Tt; t++) {
        dim3 grid(8, 16, Bn);      // 8 col tiles, 16 row tiles, batch
        lstm_step_kernel<<<grid, 256>>>(U, bvec, gamma, beta, mmean, mvar, out, t);
    }
}